// round 12
// baseline (speedup 1.0000x reference)
#include <cuda_runtime.h>

#define F_CH    64
#define HW      4096
#define BATCH   32
#define NSTAT   14
#define GSIZE   64            // blocks per channel: 32 batches x 2 half-planes
#define FPR     4             // channels per round
#define NBLK    (FPR * GSIZE) // 256 persistent blocks, single wave
#define ITERS   (F_CH / FPR)  // 16 rounds
#define HALFN   2048          // floats per half-plane

__device__ float g_part[F_CH * GSIZE * NSTAT];
__device__ unsigned int g_cnt[F_CH];   // monotonic tickets (zero-init)

__device__ __forceinline__ unsigned int ld_acq(const unsigned int* p) {
    unsigned int v;
    asm volatile("ld.acquire.gpu.global.u32 %0, [%1];" : "=r"(v) : "l"(p) : "memory");
    return v;
}

__device__ __forceinline__ void acc4(float x0, float x1, float x2, float x3, float* s) {
    s[0] += x0; s[1] += x1; s[2] += x2; s[3] += x3;
    s[4]  = fmaf(x0, x0, s[4]);
    s[5]  = fmaf(x0, x1, s[5]);
    s[6]  = fmaf(x0, x2, s[6]);
    s[7]  = fmaf(x0, x3, s[7]);
    s[8]  = fmaf(x1, x1, s[8]);
    s[9]  = fmaf(x1, x2, s[9]);
    s[10] = fmaf(x1, x3, s[10]);
    s[11] = fmaf(x2, x3, s[11]);
    s[12] = fmaf(x2, x2, s[12]);
    s[13] = fmaf(x3, x3, s[13]);
}
// s: 0..3 sums; 4:00 5:01 6:02 7:03 8:11 9:12 10:13 11:23 12:22 13:33

__device__ __forceinline__ float4 mix4(float4 v0, float4 v1, float4 v2, float4 v3,
                                       float w0, float w1, float w2, float w3, float bb) {
    float4 o;
    o.x = fmaf(w0, v0.x, fmaf(w1, v1.x, fmaf(w2, v2.x, fmaf(w3, v3.x, bb))));
    o.y = fmaf(w0, v0.y, fmaf(w1, v1.y, fmaf(w2, v2.y, fmaf(w3, v3.y, bb))));
    o.z = fmaf(w0, v0.z, fmaf(w1, v1.z, fmaf(w2, v2.z, fmaf(w3, v3.z, bb))));
    o.w = fmaf(w0, v0.w, fmaf(w1, v1.w, fmaf(w2, v2.w, fmaf(w3, v3.w, bb))));
    return o;
}

// Issue the 8 tile loads for (f, bb, half) into registers. No dependent ops:
// these stay in flight across the barrier spin that follows at the call sites.
__device__ __forceinline__ void issue_loads(const float* __restrict__ x,
                                            int f, int bb, int half, float4* t) {
    const size_t base = ((size_t)bb * 256 + f) * HW + (size_t)half * HALFN;
    const int i0 = threadIdx.x, i1 = threadIdx.x + 256;
    const float4* p0 = (const float4*)(x + base);
    const float4* p1 = (const float4*)(x + base + (size_t)64  * HW);
    const float4* p2 = (const float4*)(x + base + (size_t)128 * HW);
    const float4* p3 = (const float4*)(x + base + (size_t)192 * HW);
    t[0] = __ldcs(p0 + i0);  t[1] = __ldcs(p0 + i1);
    t[2] = __ldcs(p1 + i0);  t[3] = __ldcs(p1 + i1);
    t[4] = __ldcs(p2 + i0);  t[5] = __ldcs(p2 + i1);
    t[6] = __ldcs(p3 + i0);  t[7] = __ldcs(p3 + i1);
}

__global__ __launch_bounds__(256) void fused_qbn(const float* __restrict__ x,
                                                 const float* __restrict__ weight,
                                                 const float* __restrict__ bias,
                                                 float* __restrict__ out) {
    const int f_loc = blockIdx.x >> 6;   // 0..3
    const int sub   = blockIdx.x & 63;   // 0..63
    const int bb    = sub >> 1;          // 0..31
    const int half  = sub & 1;           // 0..1

    __shared__ float buf[4 * HALFN];     // one 32 KB tile buffer
    __shared__ float sm[8][NSTAT];
    __shared__ float AC[20];
    const int warp = threadIdx.x >> 5, lane = threadIdx.x & 31;
    const int i0 = threadIdx.x, i1 = threadIdx.x + 256;

    float4 t[8];
    issue_loads(x, f_loc, bb, half, t);  // prologue: round 0

    for (int it = 0; it < ITERS; it++) {
        const int f = it * FPR + f_loc;

        // ---- stats from the register tile (stalls on DRAM data: the bound part) ----
        float s[NSTAT];
#pragma unroll
        for (int k = 0; k < NSTAT; k++) s[k] = 0.f;
        acc4(t[0].x, t[2].x, t[4].x, t[6].x, s);
        acc4(t[0].y, t[2].y, t[4].y, t[6].y, s);
        acc4(t[0].z, t[2].z, t[4].z, t[6].z, s);
        acc4(t[0].w, t[2].w, t[4].w, t[6].w, s);
        acc4(t[1].x, t[3].x, t[5].x, t[7].x, s);
        acc4(t[1].y, t[3].y, t[5].y, t[7].y, s);
        acc4(t[1].z, t[3].z, t[5].z, t[7].z, s);
        acc4(t[1].w, t[3].w, t[5].w, t[7].w, s);

        // ---- stash tile to smem (frees t for the next round's loads) ----
        ((float4*)buf)[i0]                 = t[0];
        ((float4*)buf)[i1]                 = t[1];
        ((float4*)(buf + HALFN))[i0]       = t[2];
        ((float4*)(buf + HALFN))[i1]       = t[3];
        ((float4*)(buf + 2 * HALFN))[i0]   = t[4];
        ((float4*)(buf + 2 * HALFN))[i1]   = t[5];
        ((float4*)(buf + 3 * HALFN))[i0]   = t[6];
        ((float4*)(buf + 3 * HALFN))[i1]   = t[7];

#pragma unroll
        for (int k = 0; k < NSTAT; k++) {
#pragma unroll
            for (int off = 16; off; off >>= 1)
                s[k] += __shfl_down_sync(0xffffffffu, s[k], off);
        }
        if (lane == 0) {
#pragma unroll
            for (int k = 0; k < NSTAT; k++) sm[warp][k] = s[k];
        }
        __syncthreads();
        if (threadIdx.x < NSTAT) {
            float v = 0.f;
#pragma unroll
            for (int w = 0; w < 8; w++) v += sm[w][threadIdx.x];
            g_part[(f * GSIZE + sub) * NSTAT + threadIdx.x] = v;
            __threadfence();            // writer-side release of partials
        }
        __syncthreads();
        if (threadIdx.x == 0) atomicAdd(&g_cnt[f], 1u);   // arrive

        // ---- issue NEXT round's loads BEFORE the spin: in flight during wait ----
        if (it + 1 < ITERS)
            issue_loads(x, (it + 1) * FPR + f_loc, bb, half, t);

        // ---- wait for all 64 partners (counter multiple of GSIZE past our arrival) ----
        if (threadIdx.x == 0) {
            while (ld_acq(&g_cnt[f]) & (GSIZE - 1)) { }
        }
        __syncthreads();

        // ---- redundant per-block solve for f ----
        if (threadIdx.x < 32) {
            float r[NSTAT];
            const float* pa = &g_part[(f * GSIZE + threadIdx.x) * NSTAT];
            const float* pb = &g_part[(f * GSIZE + threadIdx.x + 32) * NSTAT];
#pragma unroll
            for (int k = 0; k < NSTAT; k++) r[k] = __ldcg(&pa[k]) + __ldcg(&pb[k]);
#pragma unroll
            for (int k = 0; k < NSTAT; k++) {
#pragma unroll
                for (int off = 16; off; off >>= 1)
                    r[k] += __shfl_down_sync(0xffffffffu, r[k], off);
            }
            if (threadIdx.x == 0) {
                const float invN = 1.0f / (float)(BATCH * HW);
                const float eps = 1e-5f;
                float m0 = r[0] * invN, m1 = r[1] * invN, m2 = r[2] * invN, m3 = r[3] * invN;
                float c00 = r[4]  * invN - m0 * m0 + eps;
                float c10 = r[5]  * invN - m0 * m1;
                float c20 = r[6]  * invN - m0 * m2;
                float c30 = r[7]  * invN - m0 * m3;
                float c11 = r[8]  * invN - m1 * m1 + eps;
                float c21 = r[9]  * invN - m1 * m2;
                float c31 = r[10] * invN - m1 * m3;
                float c32 = r[11] * invN - m2 * m3;
                float c22 = r[12] * invN - m2 * m2 + eps;
                float c33 = r[13] * invN - m3 * m3 + eps;

                float L00 = sqrtf(c00);
                float L10 = c10 / L00, L20 = c20 / L00, L30 = c30 / L00;
                float L11 = sqrtf(c11 - L10 * L10);
                float L21 = (c21 - L20 * L10) / L11;
                float L31 = (c31 - L30 * L10) / L11;
                float L22 = sqrtf(c22 - L20 * L20 - L21 * L21);
                float L32 = (c32 - L30 * L20 - L31 * L21) / L22;
                float L33 = sqrtf(c33 - L30 * L30 - L31 * L31 - L32 * L32);

                float i00f = 1.f / L00, i11f = 1.f / L11, i22f = 1.f / L22, i33f = 1.f / L33;
                float i10f = -(L10 * i00f) * i11f;
                float i20f = -(L20 * i00f + L21 * i10f) * i22f;
                float i21f = -(L21 * i11f) * i22f;
                float i30f = -(L30 * i00f + L31 * i10f + L32 * i20f) * i33f;
                float i31f = -(L31 * i11f + L32 * i21f) * i33f;
                float i32f = -(L32 * i22f) * i33f;

                float Linv[4][4] = {{i00f, 0, 0, 0},
                                    {i10f, i11f, 0, 0},
                                    {i20f, i21f, i22f, 0},
                                    {i30f, i31f, i32f, i33f}};
                float m[4] = {m0, m1, m2, m3};
#pragma unroll
                for (int i = 0; i < 4; i++) {
                    float A[4];
#pragma unroll
                    for (int j = 0; j < 4; j++) {
                        float t2 = 0.f;
#pragma unroll
                        for (int k = 0; k < 4; k++)
                            if (k >= j) t2 = fmaf(weight[(i * 4 + k) * F_CH + f], Linv[k][j], t2);
                        A[j] = t2;
                        AC[i * 4 + j] = t2;
                    }
                    AC[16 + i] = bias[i * F_CH + f]
                               - (A[0] * m[0] + A[1] * m[1] + A[2] * m[2] + A[3] * m[3]);
                }
            }
        }
        __syncthreads();

        // ---- phase 2: mix from smem tile, store with st.cs ----
        float a00 = AC[0],  a01 = AC[1],  a02 = AC[2],  a03 = AC[3];
        float a10 = AC[4],  a11 = AC[5],  a12 = AC[6],  a13 = AC[7];
        float a20 = AC[8],  a21 = AC[9],  a22 = AC[10], a23 = AC[11];
        float a30 = AC[12], a31 = AC[13], a32 = AC[14], a33 = AC[15];
        float k0 = AC[16], k1 = AC[17], k2 = AC[18], k3 = AC[19];

        const size_t base = ((size_t)bb * 256 + f) * HW + (size_t)half * HALFN;
        float4* __restrict__ q0 = (float4*)(out + base);
        float4* __restrict__ q1 = (float4*)(out + base + (size_t)64  * HW);
        float4* __restrict__ q2 = (float4*)(out + base + (size_t)128 * HW);
        float4* __restrict__ q3 = (float4*)(out + base + (size_t)192 * HW);

#pragma unroll
        for (int rep = 0; rep < 2; rep++) {
            const int i = (rep == 0) ? i0 : i1;
            float4 v0 = ((const float4*)buf)[i];
            float4 v1 = ((const float4*)(buf + HALFN))[i];
            float4 v2 = ((const float4*)(buf + 2 * HALFN))[i];
            float4 v3 = ((const float4*)(buf + 3 * HALFN))[i];
            __stcs(q0 + i, mix4(v0, v1, v2, v3, a00, a01, a02, a03, k0));
            __stcs(q1 + i, mix4(v0, v1, v2, v3, a10, a11, a12, a13, k1));
            __stcs(q2 + i, mix4(v0, v1, v2, v3, a20, a21, a22, a23, k2));
            __stcs(q3 + i, mix4(v0, v1, v2, v3, a30, a31, a32, a33, k3));
        }
        __syncthreads();   // buf/AC reuse safety before next round's stash
    }
}

extern "C" void kernel_launch(void* const* d_in, const int* in_sizes, int n_in,
                              void* d_out, int out_size) {
    const float* x      = (const float*)d_in[0];
    const float* weight = (const float*)d_in[1];
    const float* bias   = (const float*)d_in[2];
    float* out = (float*)d_out;

    fused_qbn<<<NBLK, 256>>>(x, weight, bias, out);
}

// round 13
// speedup vs baseline: 1.8017x; 1.8017x over previous
#include <cuda_runtime.h>

#define F_CH   64
#define HW     4096
#define BATCH  32
#define NSTAT  14

__device__ float g_part[F_CH * BATCH * NSTAT];  // per-(f,b) partial stats

__device__ __forceinline__ void acc4(float x0, float x1, float x2, float x3, float* s) {
    s[0] += x0; s[1] += x1; s[2] += x2; s[3] += x3;
    s[4]  = fmaf(x0, x0, s[4]);
    s[5]  = fmaf(x0, x1, s[5]);
    s[6]  = fmaf(x0, x2, s[6]);
    s[7]  = fmaf(x0, x3, s[7]);
    s[8]  = fmaf(x1, x1, s[8]);
    s[9]  = fmaf(x1, x2, s[9]);
    s[10] = fmaf(x1, x3, s[10]);
    s[11] = fmaf(x2, x3, s[11]);
    s[12] = fmaf(x2, x2, s[12]);
    s[13] = fmaf(x3, x3, s[13]);
}
// s: 0..3 sums; 4:00 5:01 6:02 7:03 8:11 9:12 10:13 11:23 12:22 13:33

// Write-through 128-bit store: minimal L2 footprint so x stays resident.
__device__ __forceinline__ void st_wt4(float4* p, float4 v) {
    asm volatile("st.global.wt.v4.f32 [%0], {%1,%2,%3,%4};"
                 :: "l"(p), "f"(v.x), "f"(v.y), "f"(v.z), "f"(v.w) : "memory");
}

// Pass 1: per-(f, batch) block accumulates 14 stats (x lands in L2 normally).
__global__ __launch_bounds__(256) void pass1_stats(const float* __restrict__ x) {
    const int f = blockIdx.x;   // 0..63
    const int bb = blockIdx.y;  // 0..31
    const size_t base = ((size_t)bb * 256 + f) * HW;
    const float4* __restrict__ p0 = (const float4*)(x + base);
    const float4* __restrict__ p1 = (const float4*)(x + base + (size_t)64  * HW);
    const float4* __restrict__ p2 = (const float4*)(x + base + (size_t)128 * HW);
    const float4* __restrict__ p3 = (const float4*)(x + base + (size_t)192 * HW);

    float s[NSTAT];
#pragma unroll
    for (int k = 0; k < NSTAT; k++) s[k] = 0.f;

#pragma unroll
    for (int half = 0; half < 2; half++) {
        const int i0 = threadIdx.x + half * 512;
        const int i1 = i0 + 256;
        float4 a0 = __ldcg(p0 + i0);
        float4 b0 = __ldcg(p1 + i0);
        float4 c0 = __ldcg(p2 + i0);
        float4 d0 = __ldcg(p3 + i0);
        float4 a1 = __ldcg(p0 + i1);
        float4 b1 = __ldcg(p1 + i1);
        float4 c1 = __ldcg(p2 + i1);
        float4 d1 = __ldcg(p3 + i1);
        acc4(a0.x, b0.x, c0.x, d0.x, s);
        acc4(a0.y, b0.y, c0.y, d0.y, s);
        acc4(a0.z, b0.z, c0.z, d0.z, s);
        acc4(a0.w, b0.w, c0.w, d0.w, s);
        acc4(a1.x, b1.x, c1.x, d1.x, s);
        acc4(a1.y, b1.y, c1.y, d1.y, s);
        acc4(a1.z, b1.z, c1.z, d1.z, s);
        acc4(a1.w, b1.w, c1.w, d1.w, s);
    }

#pragma unroll
    for (int k = 0; k < NSTAT; k++) {
#pragma unroll
        for (int off = 16; off; off >>= 1)
            s[k] += __shfl_down_sync(0xffffffffu, s[k], off);
    }

    __shared__ float sm[8][NSTAT];
    const int warp = threadIdx.x >> 5, lane = threadIdx.x & 31;
    if (lane == 0) {
#pragma unroll
        for (int k = 0; k < NSTAT; k++) sm[warp][k] = s[k];
    }
    __syncthreads();
    if (threadIdx.x < NSTAT) {
        float t = 0.f;
#pragma unroll
        for (int w = 0; w < 8; w++) t += sm[w][threadIdx.x];
        g_part[(f * BATCH + bb) * NSTAT + threadIdx.x] = t;
    }
}

__device__ __forceinline__ float4 mix4(float4 v0, float4 v1, float4 v2, float4 v3,
                                       float w0, float w1, float w2, float w3, float bb) {
    float4 o;
    o.x = fmaf(w0, v0.x, fmaf(w1, v1.x, fmaf(w2, v2.x, fmaf(w3, v3.x, bb))));
    o.y = fmaf(w0, v0.y, fmaf(w1, v1.y, fmaf(w2, v2.y, fmaf(w3, v3.y, bb))));
    o.z = fmaf(w0, v0.z, fmaf(w1, v1.z, fmaf(w2, v2.z, fmaf(w3, v3.z, bb))));
    o.w = fmaf(w0, v0.w, fmaf(w1, v1.w, fmaf(w2, v2.w, fmaf(w3, v3.w, bb))));
    return o;
}

// Pass 2: REVERSE block order (hit pass1's still-resident tail of x in L2),
// per-block redundant solve, fused whitening + affine with WRITE-THROUGH stores.
__global__ __launch_bounds__(256) void pass2_apply(const float* __restrict__ x,
                                                   const float* __restrict__ weight,
                                                   const float* __restrict__ bias,
                                                   float* __restrict__ out) {
    const int rlin = (F_CH * BATCH - 1) - (blockIdx.y * F_CH + blockIdx.x);
    const int f  = rlin % F_CH;
    const int bb = rlin / F_CH;
    __shared__ float AC[20];

    if (threadIdx.x < 32) {
        const int lane = threadIdx.x;
        float s[NSTAT];
#pragma unroll
        for (int k = 0; k < NSTAT; k++) s[k] = g_part[(f * BATCH + lane) * NSTAT + k];
#pragma unroll
        for (int k = 0; k < NSTAT; k++) {
#pragma unroll
            for (int off = 16; off; off >>= 1)
                s[k] += __shfl_down_sync(0xffffffffu, s[k], off);
        }
        if (lane == 0) {
            const float invN = 1.0f / (float)(BATCH * HW);
            const float eps = 1e-5f;
            float m0 = s[0] * invN, m1 = s[1] * invN, m2 = s[2] * invN, m3 = s[3] * invN;
            float c00 = s[4]  * invN - m0 * m0 + eps;
            float c10 = s[5]  * invN - m0 * m1;
            float c20 = s[6]  * invN - m0 * m2;
            float c30 = s[7]  * invN - m0 * m3;
            float c11 = s[8]  * invN - m1 * m1 + eps;
            float c21 = s[9]  * invN - m1 * m2;
            float c31 = s[10] * invN - m1 * m3;
            float c32 = s[11] * invN - m2 * m3;
            float c22 = s[12] * invN - m2 * m2 + eps;
            float c33 = s[13] * invN - m3 * m3 + eps;

            float L00 = sqrtf(c00);
            float L10 = c10 / L00, L20 = c20 / L00, L30 = c30 / L00;
            float L11 = sqrtf(c11 - L10 * L10);
            float L21 = (c21 - L20 * L10) / L11;
            float L31 = (c31 - L30 * L10) / L11;
            float L22 = sqrtf(c22 - L20 * L20 - L21 * L21);
            float L32 = (c32 - L30 * L20 - L31 * L21) / L22;
            float L33 = sqrtf(c33 - L30 * L30 - L31 * L31 - L32 * L32);

            float i00 = 1.f / L00, i11 = 1.f / L11, i22 = 1.f / L22, i33 = 1.f / L33;
            float i10 = -(L10 * i00) * i11;
            float i20 = -(L20 * i00 + L21 * i10) * i22;
            float i21 = -(L21 * i11) * i22;
            float i30 = -(L30 * i00 + L31 * i10 + L32 * i20) * i33;
            float i31 = -(L31 * i11 + L32 * i21) * i33;
            float i32 = -(L32 * i22) * i33;

            float Linv[4][4] = {{i00, 0, 0, 0},
                                {i10, i11, 0, 0},
                                {i20, i21, i22, 0},
                                {i30, i31, i32, i33}};
            float m[4] = {m0, m1, m2, m3};
#pragma unroll
            for (int i = 0; i < 4; i++) {
                float A[4];
#pragma unroll
                for (int j = 0; j < 4; j++) {
                    float t = 0.f;
#pragma unroll
                    for (int k = 0; k < 4; k++)
                        if (k >= j) t = fmaf(weight[(i * 4 + k) * F_CH + f], Linv[k][j], t);
                    A[j] = t;
                    AC[i * 4 + j] = t;
                }
                AC[16 + i] = bias[i * F_CH + f]
                           - (A[0] * m[0] + A[1] * m[1] + A[2] * m[2] + A[3] * m[3]);
            }
        }
    }
    __syncthreads();

    float a00 = AC[0],  a01 = AC[1],  a02 = AC[2],  a03 = AC[3];
    float a10 = AC[4],  a11 = AC[5],  a12 = AC[6],  a13 = AC[7];
    float a20 = AC[8],  a21 = AC[9],  a22 = AC[10], a23 = AC[11];
    float a30 = AC[12], a31 = AC[13], a32 = AC[14], a33 = AC[15];
    float c0 = AC[16], c1 = AC[17], c2 = AC[18], c3 = AC[19];

    const size_t base = ((size_t)bb * 256 + f) * HW;
    const float4* __restrict__ p0 = (const float4*)(x + base);
    const float4* __restrict__ p1 = (const float4*)(x + base + (size_t)64  * HW);
    const float4* __restrict__ p2 = (const float4*)(x + base + (size_t)128 * HW);
    const float4* __restrict__ p3 = (const float4*)(x + base + (size_t)192 * HW);
    float4* __restrict__ q0 = (float4*)(out + base);
    float4* __restrict__ q1 = (float4*)(out + base + (size_t)64  * HW);
    float4* __restrict__ q2 = (float4*)(out + base + (size_t)128 * HW);
    float4* __restrict__ q3 = (float4*)(out + base + (size_t)192 * HW);

#pragma unroll
    for (int half = 0; half < 2; half++) {
        const int i0 = threadIdx.x + half * 512;
        const int i1 = i0 + 256;
        float4 v0 = __ldcg(p0 + i0);
        float4 v1 = __ldcg(p1 + i0);
        float4 v2 = __ldcg(p2 + i0);
        float4 v3 = __ldcg(p3 + i0);
        float4 w0 = __ldcg(p0 + i1);
        float4 w1 = __ldcg(p1 + i1);
        float4 w2 = __ldcg(p2 + i1);
        float4 w3 = __ldcg(p3 + i1);
        st_wt4(q0 + i0, mix4(v0, v1, v2, v3, a00, a01, a02, a03, c0));
        st_wt4(q1 + i0, mix4(v0, v1, v2, v3, a10, a11, a12, a13, c1));
        st_wt4(q2 + i0, mix4(v0, v1, v2, v3, a20, a21, a22, a23, c2));
        st_wt4(q3 + i0, mix4(v0, v1, v2, v3, a30, a31, a32, a33, c3));
        st_wt4(q0 + i1, mix4(w0, w1, w2, w3, a00, a01, a02, a03, c0));
        st_wt4(q1 + i1, mix4(w0, w1, w2, w3, a10, a11, a12, a13, c1));
        st_wt4(q2 + i1, mix4(w0, w1, w2, w3, a20, a21, a22, a23, c2));
        st_wt4(q3 + i1, mix4(w0, w1, w2, w3, a30, a31, a32, a33, c3));
    }
}

extern "C" void kernel_launch(void* const* d_in, const int* in_sizes, int n_in,
                              void* d_out, int out_size) {
    const float* x      = (const float*)d_in[0];
    const float* weight = (const float*)d_in[1];
    const float* bias   = (const float*)d_in[2];
    float* out = (float*)d_out;

    dim3 grid(F_CH, BATCH);
    pass1_stats<<<grid, 256>>>(x);
    pass2_apply<<<grid, 256>>>(x, weight, bias, out);
}